// round 1
// baseline (speedup 1.0000x reference)
#include <cuda_runtime.h>
#include <cuda_bf16.h>

#define NPROJ 360
#define DH 512
#define DW 512
#define VZ 128
#define VY 128
#define VX 128

__global__ __launch_bounds__(512)
void cbp_kernel(const float* __restrict__ sino,
                const float* __restrict__ origin,
                const float* __restrict__ spacing,
                const float* __restrict__ traj,
                const float* __restrict__ pm_p,
                float* __restrict__ out)
{
    __shared__ float sP[NPROJ * 12];

    const int tid = threadIdx.y * 128 + threadIdx.x;
    for (int i = tid; i < NPROJ * 12; i += 512)
        sP[i] = traj[i];
    __syncthreads();

    const int x = threadIdx.x;                 // warp lanes adjacent in x
    const int y = blockIdx.y * 4 + threadIdx.y;
    const int z = blockIdx.z;

    const float wx = origin[2] + spacing[2] * (float)x;
    const float wy = origin[1] + spacing[1] * (float)y;
    const float wz = origin[0] + spacing[0] * (float)z;
    const float pm = *pm_p;

    float acc = 0.0f;

    #pragma unroll 2
    for (int p = 0; p < NPROJ; ++p) {
        const float4* P4 = reinterpret_cast<const float4*>(sP + p * 12);
        const float4 r0 = P4[0];   // P00 P01 P02 P03
        const float4 r1 = P4[1];   // P10 P11 P12 P13
        const float4 r2 = P4[2];   // P20 P21 P22 P23

        float un = fmaf(r0.x, wx, fmaf(r0.y, wy, fmaf(r0.z, wz, r0.w)));
        float vn = fmaf(r1.x, wx, fmaf(r1.y, wy, fmaf(r1.z, wz, r1.w)));
        float t  = fmaf(r2.x, wx, fmaf(r2.y, wy, fmaf(r2.z, wz, r2.w)));

        float rt = __fdividef(1.0f, t);        // MUFU.RCP, ~2^-22 rel err
        float u = un * rt;
        float v = vn * rt;

        if (u >= 0.0f && u <= (float)(DW - 1) && v >= 0.0f && v <= (float)(DH - 1)) {
            // inside valid region floor == trunc (u,v >= 0)
            int u0 = (int)u;
            int v0 = (int)v;
            float fu = u - (float)u0;
            float fv = v - (float)v0;
            int u1 = min(u0 + 1, DW - 1);
            int v1 = min(v0 + 1, DH - 1);

            const float* img = sino + (size_t)p * (DH * DW);
            const int b0 = v0 * DW;
            const int b1 = v1 * DW;
            float a00 = __ldg(img + b0 + u0);
            float a01 = __ldg(img + b0 + u1);
            float a10 = __ldg(img + b1 + u0);
            float a11 = __ldg(img + b1 + u1);

            float top = fmaf(fu, a01 - a00, a00);
            float bot = fmaf(fu, a11 - a10, a10);
            float val = fmaf(fv, bot - top, top);

            acc = fmaf(val, pm * rt * rt, acc);
        }
    }

    out[((size_t)z * VY + y) * VX + x] = acc;
}

extern "C" void kernel_launch(void* const* d_in, const int* in_sizes, int n_in,
                              void* d_out, int out_size)
{
    // metadata order:
    // 0: input sino   f32 [1,360,512,512]
    // 1: volume_shape i64 [3]    (compile-time constants; unused on device)
    // 2: volume_origin f32 [3]
    // 3: volume_spacing f32 [3]
    // 4: trajectory   f32 [360,3,4]
    // 5: projection_multiplier f32 [1]
    // 6: step_size    f32 [1]   (unused by reference)
    const float* sino    = (const float*)d_in[0];
    const float* origin  = (const float*)d_in[2];
    const float* spacing = (const float*)d_in[3];
    const float* traj    = (const float*)d_in[4];
    const float* pm      = (const float*)d_in[5];
    float* out           = (float*)d_out;

    dim3 block(128, 4, 1);
    dim3 grid(1, VY / 4, VZ);
    cbp_kernel<<<grid, block>>>(sino, origin, spacing, traj, pm, out);
}

// round 7
// speedup vs baseline: 1.1047x; 1.1047x over previous
#include <cuda_runtime.h>
#include <cuda_fp16.h>

#define NPROJ 360
#define DH 512
#define DW 512
#define VZ 128
#define VY 128
#define VX 128

// Quad-packed fp16 sinogram: for each (p, v, u) store the 2x2 bilinear
// footprint {s[v][u], s[v][u1]} , {s[v1][u], s[v1][u1]} (u1/v1 edge-clamped)
// as two half2 in a uint2 (8 bytes). 360*512*512*8B = 755 MB scratch.
__device__ uint2 g_pack[(size_t)NPROJ * DH * DW];

__global__ __launch_bounds__(256)
void pack_kernel(const float* __restrict__ sino)
{
    int idx = blockIdx.x * 256 + threadIdx.x;          // < 360*512*512 = 94371840
    int u = idx & (DW - 1);
    int v = (idx >> 9) & (DH - 1);
    int p = idx >> 18;

    const float* img0 = sino + (size_t)p * (DH * DW) + v * DW;
    const float* img1 = img0 + ((v < DH - 1) ? DW : 0);
    int u1 = (u < DW - 1) ? (u + 1) : u;

    float a00 = __ldg(img0 + u);
    float a01 = __ldg(img0 + u1);
    float a10 = __ldg(img1 + u);
    float a11 = __ldg(img1 + u1);

    __half2 lo = __floats2half2_rn(a00, a01);   // row v
    __half2 hi = __floats2half2_rn(a10, a11);   // row v+1
    uint2 w;
    w.x = *reinterpret_cast<unsigned*>(&lo);
    w.y = *reinterpret_cast<unsigned*>(&hi);
    g_pack[idx] = w;
}

__global__ __launch_bounds__(512)
void cbp_kernel(const float* __restrict__ origin,
                const float* __restrict__ spacing,
                const float* __restrict__ traj,
                const float* __restrict__ pm_p,
                float* __restrict__ out)
{
    __shared__ float sP[NPROJ * 12];

    const int tid = threadIdx.y * 128 + threadIdx.x;
    for (int i = tid; i < NPROJ * 12; i += 512)
        sP[i] = traj[i];
    __syncthreads();

    const int x = threadIdx.x;                 // warp lanes adjacent in x
    const int y = blockIdx.y * 4 + threadIdx.y;
    const int z = blockIdx.z;

    const float wx = origin[2] + spacing[2] * (float)x;
    const float wy = origin[1] + spacing[1] * (float)y;
    const float wz = origin[0] + spacing[0] * (float)z;
    const float pm = *pm_p;

    float acc = 0.0f;

    #pragma unroll 2
    for (int p = 0; p < NPROJ; ++p) {
        const float4* P4 = reinterpret_cast<const float4*>(sP + p * 12);
        const float4 r0 = P4[0];
        const float4 r1 = P4[1];
        const float4 r2 = P4[2];

        float un = fmaf(r0.x, wx, fmaf(r0.y, wy, fmaf(r0.z, wz, r0.w)));
        float vn = fmaf(r1.x, wx, fmaf(r1.y, wy, fmaf(r1.z, wz, r1.w)));
        float t  = fmaf(r2.x, wx, fmaf(r2.y, wy, fmaf(r2.z, wz, r2.w)));

        float rt = __fdividef(1.0f, t);        // MUFU.RCP
        float u = un * rt;
        float v = vn * rt;

        if (u >= 0.0f && u <= (float)(DW - 1) && v >= 0.0f && v <= (float)(DH - 1)) {
            int u0 = (int)u;                   // u,v >= 0 -> trunc == floor
            int v0 = (int)v;
            float fu = u - (float)u0;
            float fv = v - (float)v0;

            uint2 w = __ldg(&g_pack[((size_t)p << 18) | (unsigned)((v0 << 9) | u0)]);
            __half2 lo = *reinterpret_cast<__half2*>(&w.x);
            __half2 hi = *reinterpret_cast<__half2*>(&w.y);
            float2 r0v = __half22float2(lo);   // (a00, a01)
            float2 r1v = __half22float2(hi);   // (a10, a11)

            float top = fmaf(fu, r0v.y - r0v.x, r0v.x);
            float bot = fmaf(fu, r1v.y - r1v.x, r1v.x);
            float val = fmaf(fv, bot - top, top);

            acc = fmaf(val, pm * rt * rt, acc);
        }
    }

    out[((size_t)z * VY + y) * VX + x] = acc;
}

extern "C" void kernel_launch(void* const* d_in, const int* in_sizes, int n_in,
                              void* d_out, int out_size)
{
    const float* sino    = (const float*)d_in[0];
    const float* origin  = (const float*)d_in[2];
    const float* spacing = (const float*)d_in[3];
    const float* traj    = (const float*)d_in[4];
    const float* pm      = (const float*)d_in[5];
    float* out           = (float*)d_out;

    // Prepass: build quad-packed fp16 sinogram (deterministic, rebuilt every call)
    const int total = NPROJ * DH * DW;
    pack_kernel<<<total / 256, 256>>>(sino);

    dim3 block(128, 4, 1);
    dim3 grid(1, VY / 4, VZ);
    cbp_kernel<<<grid, block>>>(origin, spacing, traj, pm, out);
}